// round 1
// baseline (speedup 1.0000x reference)
#include <cuda_runtime.h>

// 3x3 stride-1 pad-1 conv, NCHW fp32: x[16,32,256,256] * w[32,32,3,3] + b[32].
// Strategy: direct conv, f32x2 packed FMA (FFMA2) pairing output channels.
//  - Block = 32(w) x 16(h) spatial tile for one image, ALL 32 output channels.
//  - 256 threads = 8 warps; warp handles 2 output rows; lane = x position
//    (=> fully coalesced global stores).
//  - Each lane holds 32 f32x2 accumulators: acc[2 rows][16 oc-pairs].
//  - Weights pre-packed in smem as {w[oc=2p], w[oc=2p+1]} u64 pairs -> one
//    broadcast LDS.64 per 2 MACs. Inputs duplicated {v,v} (12 packs per ic).
//  - Input channels streamed in chunks of 4 through a small smem halo tile.
// FP32 math is exact FMA per half -> rel_err vs reference ~1e-6.

#define HW   256
#define ICN  32
#define OCN  32
#define NB   16
#define TW   32
#define TH   16
#define ICC  4
#define XROWS (TH + 2)   // 18
#define XCOLS (TW + 2)   // 34

typedef unsigned long long u64;

__device__ __forceinline__ u64 pack2(float lo, float hi) {
    u64 d;
    asm("mov.b64 %0, {%1, %2};" : "=l"(d) : "f"(lo), "f"(hi));
    return d;
}
__device__ __forceinline__ void fma2(u64 &acc, u64 a, u64 b) {
    asm("fma.rn.f32x2 %0, %1, %2, %0;" : "+l"(acc) : "l"(a), "l"(b));
}
__device__ __forceinline__ void unpack2(u64 v, float &lo, float &hi) {
    asm("mov.b64 {%0, %1}, %2;" : "=f"(lo), "=f"(hi) : "l"(v));
}

__global__ __launch_bounds__(256, 2)
void conv3x3_f32x2_kernel(const float* __restrict__ xg,
                          const float* __restrict__ wg,
                          const float* __restrict__ bg,
                          float* __restrict__ out)
{
    // 36,864 B weights (oc-paired) + 9,792 B input chunk = 46,656 B static smem
    __shared__ u64   ws2[ICN][OCN / 2][9];
    __shared__ float xs[ICC][XROWS][XCOLS];

    const int tid  = threadIdx.x;
    const int lane = tid & 31;
    const int warp = tid >> 5;
    const int bx = blockIdx.x, by = blockIdx.y, n = blockIdx.z;

    // ---- Pre-pack weights into oc-pairs: ws2[ic][p][k] = {w[2p][ic][k], w[2p+1][ic][k]}
    for (int idx = tid; idx < ICN * 16 * 9; idx += 256) {
        int k  = idx % 9;
        int p  = (idx / 9) & 15;
        int ic = idx / 144;
        float w0 = wg[((2 * p)     * ICN + ic) * 9 + k];
        float w1 = wg[((2 * p + 1) * ICN + ic) * 9 + k];
        ws2[ic][p][k] = pack2(w0, w1);
    }

    // ---- Accumulators init with bias (pair over oc)
    u64 acc[2][16];
    #pragma unroll
    for (int p = 0; p < 16; p++) {
        u64 bp = pack2(bg[2 * p], bg[2 * p + 1]);
        acc[0][p] = bp;
        acc[1][p] = bp;
    }

    const int r0     = warp * 2;        // output rows r0, r0+1 within the tile
    const int gx     = bx * TW + lane;  // global x (lane-coalesced)
    const int y_base = by * TH;

    #pragma unroll 1
    for (int c = 0; c < ICN / ICC; c++) {
        __syncthreads();  // previous chunk's readers done (also orders ws2 fill on c==0)

        // ---- Fill input halo tile for ic = c*ICC .. c*ICC+3 (zero-padded borders)
        for (int idx = tid; idx < ICC * XROWS * XCOLS; idx += 256) {
            int col = idx % XCOLS;
            int row = (idx / XCOLS) % XROWS;
            int icl = idx / (XCOLS * XROWS);
            int gy  = y_base + row - 1;
            int gxx = bx * TW + col - 1;
            float v = 0.f;
            if ((unsigned)gy < HW && (unsigned)gxx < HW)
                v = xg[((n * ICN + c * ICC + icl) * HW + gy) * HW + gxx];
            xs[icl][row][col] = v;
        }
        __syncthreads();

        #pragma unroll 1
        for (int icl = 0; icl < ICC; icl++) {
            // 12 input values (4 halo rows x 3 x-offsets), duplicated into both halves
            u64 ip[4][3];
            #pragma unroll
            for (int j = 0; j < 4; j++) {
                #pragma unroll
                for (int dx = 0; dx < 3; dx++) {
                    float v = xs[icl][r0 + j][lane + dx];
                    ip[j][dx] = pack2(v, v);
                }
            }
            const u64* wp = &ws2[c * ICC + icl][0][0];
            #pragma unroll
            for (int p = 0; p < 16; p++) {
                #pragma unroll
                for (int dy = 0; dy < 3; dy++) {
                    #pragma unroll
                    for (int dx = 0; dx < 3; dx++) {
                        u64 w = wp[p * 9 + dy * 3 + dx];   // broadcast LDS.64
                        fma2(acc[0][p], w, ip[dy][dx]);     // output row r0
                        fma2(acc[1][p], w, ip[dy + 1][dx]); // output row r0+1
                    }
                }
            }
        }
    }

    // ---- Coalesced stores: lane = x, loop over oc planes
    #pragma unroll
    for (int row = 0; row < 2; row++) {
        int gy = y_base + r0 + row;
        #pragma unroll
        for (int p = 0; p < 16; p++) {
            float lo, hi;
            unpack2(acc[row][p], lo, hi);
            out[((n * OCN + 2 * p)     * HW + gy) * HW + gx] = lo;
            out[((n * OCN + 2 * p + 1) * HW + gy) * HW + gx] = hi;
        }
    }
}

extern "C" void kernel_launch(void* const* d_in, const int* in_sizes, int n_in,
                              void* d_out, int out_size) {
    const float* x = (const float*)d_in[0];
    const float* w = (const float*)d_in[1];
    const float* b = (const float*)d_in[2];
    float* out = (float*)d_out;

    dim3 grid(HW / TW, HW / TH, NB);   // (8, 16, 16) = 2048 blocks
    conv3x3_f32x2_kernel<<<grid, 256>>>(x, w, b, out);
}

// round 3
// speedup vs baseline: 1.2162x; 1.2162x over previous
#include <cuda_runtime.h>
#include <cstdint>

// 3x3 s1 p1 conv, NCHW fp32 x[16,32,256,256] * w[32,32,3,3] + b[32]
// via mma.sync.m16n8k8 TF32 (plain PTX ISA - compiles at compute_103).
// 9 shifted GEMMs: D[128px, 32oc] += A_{dy,dx}[128px, 32ic] x W_{dy,dx}[32ic, 32oc].
// CTA = 128-wide x-strip x 8 output rows x 1 image. dy handled by a 3-row ring of
// A tiles; each ring slot holds 3 dx-shifted copies, stored in *fragment order*
// (one LDS.128 per A fragment). Weights in fragment order (LDS.64 per frag).
// Epilogue: C regs -> padded smem scratch (conflict-free) -> coalesced STG.128.

#define HW   256
#define ICN  32
#define OCN  32
#define YCH  8

#define SM_BIAS    0
#define SM_B       128
#define B_BYTES    (9 * 4 * 4 * 32 * 8)      // tap*kstep*ntile*lane*float2 = 36864
#define SM_A       (SM_B + B_BYTES)          // 36992
#define SLOT_BYTES (3 * 4 * 8 * 32 * 16)     // dx*kstep*mtile*lane*float4 = 49152
#define SM_SCR     (SM_A + 3 * SLOT_BYTES)   // 184448
#define SCR_STRIDE 132                       // floats per oc row (pad: bank=(4*oc+px)&31)
#define SMEM_TOTAL (SM_SCR + OCN * SCR_STRIDE * 4)   // 201344 B

__device__ __forceinline__ uint32_t f2tf(float f) {
    uint32_t r;
    asm("cvt.rna.tf32.f32 %0, %1;" : "=r"(r) : "f"(f));
    return r;
}

__device__ __forceinline__ void mma8(float c[4], uint32_t a0, uint32_t a1,
                                     uint32_t a2, uint32_t a3,
                                     uint32_t b0, uint32_t b1) {
    asm volatile(
        "mma.sync.aligned.m16n8k8.row.col.f32.tf32.tf32.f32 "
        "{%0,%1,%2,%3},{%4,%5,%6,%7},{%8,%9},{%0,%1,%2,%3};"
        : "+f"(c[0]), "+f"(c[1]), "+f"(c[2]), "+f"(c[3])
        : "r"(a0), "r"(a1), "r"(a2), "r"(a3), "r"(b0), "r"(b1));
}

// Stage input row yin into ring slot (yin%3): 3 dx shifts, fragment order.
// Frag float4 for (dx, kstep k, mtile m, lane) = { x(ic,px), x(ic,px+8), x(ic+4,px), x(ic+4,px+8) }
// with ic = k*8 + (lane&3), px = m*16 + (lane>>2) + dx - 1 (global x; OOB -> 0).
__device__ __forceinline__ void build_slot(const float* __restrict__ xn, int yin,
                                           int x0, char* smem, int tid) {
    int s = (yin + 3) % 3;
    char* base = smem + SM_A + s * SLOT_BYTES;
    bool yok = ((unsigned)yin < HW);
    const float* xrow = xn + ((size_t)yin << 8);
    #pragma unroll
    for (int it = 0; it < 12; it++) {
        int idx  = tid + it * 256;
        int lane = idx & 31;
        int m    = (idx >> 5) & 7;
        int k    = (idx >> 8) & 3;
        int dx   = idx >> 10;
        int ic   = k * 8 + (lane & 3);
        int gx   = x0 + m * 16 + (lane >> 2) + dx - 1;
        uint4 v = make_uint4(0u, 0u, 0u, 0u);
        if (yok) {
            const float* p = xrow + ((size_t)ic << 16) + gx;
            if ((unsigned)gx < HW)       { v.x = f2tf(p[0]); v.z = f2tf(p[4 << 16]); }
            if ((unsigned)(gx + 8) < HW) { v.y = f2tf(p[8]); v.w = f2tf(p[(4 << 16) + 8]); }
        }
        *(uint4*)(base + ((((dx * 4 + k) * 8 + m) * 32 + lane) << 4)) = v;
    }
}

__global__ __launch_bounds__(256, 1)
void conv3x3_tf32_mma_kernel(const float* __restrict__ xg,
                             const float* __restrict__ wg,
                             const float* __restrict__ bg,
                             float* __restrict__ out)
{
    extern __shared__ char smem[];
    const int tid  = threadIdx.x;
    const int warp = tid >> 5;
    const int lane = tid & 31;

    const int x0 = blockIdx.x * 128;
    const int y0 = blockIdx.y * YCH;
    const int n  = blockIdx.z;
    const float* xn = xg + (((size_t)n * ICN) << 16);

    // ---- Bias + weights (fragment order), once per CTA
    if (tid < OCN) ((float*)(smem + SM_BIAS))[tid] = bg[tid];
    #pragma unroll
    for (int it = 0; it < 18; it++) {
        int idx  = tid + it * 256;                 // 4608 float2 frags
        int l    = idx & 31;
        int nt   = (idx >> 5) & 3;
        int k    = (idx >> 7) & 3;
        int tap  = idx >> 9;                       // dy*3+dx
        int oc   = nt * 8 + (l >> 2);
        int ic   = k * 8 + (l & 3);
        uint2 w2;
        w2.x = f2tf(wg[(oc * ICN + ic) * 9 + tap]);
        w2.y = f2tf(wg[(oc * ICN + ic + 4) * 9 + tap]);
        *(uint2*)(smem + SM_B + ((((tap * 4 + k) * 4 + nt) * 32 + l) << 3)) = w2;
    }

    // ---- Prologue: stage input rows y0-1 and y0
    build_slot(xn, y0 - 1, x0, smem, tid);
    build_slot(xn, y0,     x0, smem, tid);

    float* scr = (float*)(smem + SM_SCR);
    const float bv = ((float*)(smem + SM_BIAS))[tid >> 3];   // epilogue: oc = tid>>3

    #pragma unroll 1
    for (int y = y0; y < y0 + YCH; y++) {
        build_slot(xn, y + 1, x0, smem, tid);   // slot (y+1)%3; its prior reader was mma(y-1)
        __syncthreads();

        float c[4][4];
        #pragma unroll
        for (int nt = 0; nt < 4; nt++)
            #pragma unroll
            for (int i = 0; i < 4; i++) c[nt][i] = 0.f;

        const uint4* aw = (const uint4*)(smem + SM_A) + (size_t)warp * 32 + lane;
        const uint2* bw = (const uint2*)(smem + SM_B) + lane;

        #pragma unroll
        for (int dy = 0; dy < 3; dy++) {
            int s = (y - 1 + dy + 3) % 3;
            const uint4* aslot = aw + s * (SLOT_BYTES / 16);
            #pragma unroll
            for (int dx = 0; dx < 3; dx++) {
                int tap = dy * 3 + dx;
                #pragma unroll
                for (int k = 0; k < 4; k++) {
                    uint4 a = aslot[(size_t)(dx * 4 + k) * 256];   // (dx*4+k)*8mtiles*32lanes
                    #pragma unroll
                    for (int nt = 0; nt < 4; nt++) {
                        uint2 b = bw[(size_t)(((tap * 4 + k) * 4 + nt)) * 32];
                        mma8(c[nt], a.x, a.y, a.z, a.w, b.x, b.y);
                    }
                }
            }
        }

        // ---- C frags -> scratch[oc][px] (stride 132 floats: conflict-free STS.32)
        {
            int g = lane >> 2, t = lane & 3;
            int px0 = warp * 16 + g;
            #pragma unroll
            for (int nt = 0; nt < 4; nt++) {
                int oc0 = nt * 8 + 2 * t;
                scr[oc0 * SCR_STRIDE + px0]           = c[nt][0];
                scr[(oc0 + 1) * SCR_STRIDE + px0]     = c[nt][1];
                scr[oc0 * SCR_STRIDE + px0 + 8]       = c[nt][2];
                scr[(oc0 + 1) * SCR_STRIDE + px0 + 8] = c[nt][3];
            }
        }
        __syncthreads();

        // ---- Coalesced store: thread -> (oc = tid>>3, 16 px), +bias
        {
            int oc  = tid >> 3;
            int pxb = (tid & 7) * 16;
            const float* srow = scr + oc * SCR_STRIDE + pxb;
            float* orow = out + (((size_t)n * OCN + oc) << 16) + (y << 8) + x0 + pxb;
            #pragma unroll
            for (int i = 0; i < 4; i++) {
                float4 v = *(const float4*)(srow + 4 * i);
                v.x += bv; v.y += bv; v.z += bv; v.w += bv;
                *(float4*)(orow + 4 * i) = v;
            }
        }
    }
}

extern "C" void kernel_launch(void* const* d_in, const int* in_sizes, int n_in,
                              void* d_out, int out_size) {
    const float* x = (const float*)d_in[0];
    const float* w = (const float*)d_in[1];
    const float* b = (const float*)d_in[2];
    float* out = (float*)d_out;

    cudaFuncSetAttribute(conv3x3_tf32_mma_kernel,
                         cudaFuncAttributeMaxDynamicSharedMemorySize, SMEM_TOTAL);

    dim3 grid(HW / 128, HW / YCH, 16);   // (2, 32, 16) = 1024 CTAs
    conv3x3_tf32_mma_kernel<<<grid, 256, SMEM_TOTAL>>>(x, w, b, out);
}

// round 4
// speedup vs baseline: 3.0340x; 2.4947x over previous
#include <cuda_runtime.h>
#include <cstdint>

// 3x3 s1 p1 conv, NCHW fp32 via mma.sync.m16n8k8 TF32.
// CTA = 64-px x-strip x 8 output rows x 1 image; 256 thr / 8 warps.
// Warp = 1 m-tile (16 px) x 2 n-tiles (16 oc), row-PAIR inner loop (C = 16 regs).
// A: canonical [ic][px] tiles (stride 72 floats -> conflict-free LDS.32 frag
//    gathers, no dx triplication), 4-slot row ring, 36.9 KB.
// B: fragment-order smem (36 KB), 6 frags cached in regs per (k,dx).
// Total smem 73.7 KB -> 2 CTAs/SM. Epilogue: direct sector-perfect STG.32 + bias.

#define HW     256
#define ICN    32
#define OCN    32
#define SW     64            // strip width
#define XW     66            // strip + halo
#define STRIDE 72            // floats per ic row (==8 mod 32 -> conflict-free)
#define SLOT_F (ICN * STRIDE)            // 2304 floats = 9216 B
#define B_BYTES (9 * 4 * 4 * 32 * 8)     // 36864
#define SM_A    B_BYTES
#define SMEM_TOTAL (B_BYTES + 4 * SLOT_F * 4)   // 73728 B

__device__ __forceinline__ uint32_t f2tf(float f) {
    uint32_t r;
    asm("cvt.rna.tf32.f32 %0, %1;" : "=r"(r) : "f"(f));
    return r;
}

__device__ __forceinline__ void mma8(float c[4], uint32_t a0, uint32_t a1,
                                     uint32_t a2, uint32_t a3, uint2 b) {
    asm volatile(
        "mma.sync.aligned.m16n8k8.row.col.f32.tf32.tf32.f32 "
        "{%0,%1,%2,%3},{%4,%5,%6,%7},{%8,%9},{%0,%1,%2,%3};"
        : "+f"(c[0]), "+f"(c[1]), "+f"(c[2]), "+f"(c[3])
        : "r"(a0), "r"(a1), "r"(a2), "r"(a3), "r"(b.x), "r"(b.y));
}

// Stage input row yin into ring slot (yin&3): raw tf32 [ic][px], coalesced.
__device__ __forceinline__ void build_row(const float* __restrict__ xn, int yin,
                                          int x0, uint32_t* __restrict__ smA,
                                          int tid) {
    uint32_t* slot = smA + ((yin + 4) & 3) * SLOT_F;
    bool yok = ((unsigned)yin < HW);
    const float* xr = xn + ((size_t)yin << 8);
    #pragma unroll
    for (int e = tid; e < ICN * XW; e += 256) {
        int ic = e / XW;
        int px = e - ic * XW;
        int gx = x0 - 1 + px;
        float v = 0.f;
        if (yok && (unsigned)gx < HW) v = xr[((size_t)ic << 16) + gx];
        slot[ic * STRIDE + px] = f2tf(v);
    }
}

__global__ __launch_bounds__(256, 2)
void conv3x3_tf32_mma2_kernel(const float* __restrict__ xg,
                              const float* __restrict__ wg,
                              const float* __restrict__ bg,
                              float* __restrict__ out)
{
    extern __shared__ char smem[];
    uint32_t* smA = (uint32_t*)(smem + SM_A);
    const int tid  = threadIdx.x;
    const int warp = tid >> 5;
    const int lane = tid & 31;
    const int mt   = warp >> 1;     // m-tile 0..3
    const int nth  = warp & 1;      // n-tile half: nt in {2*nth, 2*nth+1}

    const int x0 = blockIdx.x * SW;
    const int y0 = blockIdx.y * 8;
    const int n  = blockIdx.z;
    const float* xn = xg + (((size_t)n * ICN) << 16);

    // ---- Stage B (fragment order), once per CTA: 4608 uint2 frags
    #pragma unroll
    for (int it = 0; it < 18; it++) {
        int idx  = tid + it * 256;
        int l    = idx & 31;
        int nt   = (idx >> 5) & 3;
        int k    = (idx >> 7) & 3;
        int tap  = idx >> 9;                    // dy*3+dx
        int oc   = nt * 8 + (l >> 2);
        int ic   = k * 8 + (l & 3);
        uint2 w2;
        w2.x = f2tf(wg[(oc * ICN + ic) * 9 + tap]);
        w2.y = f2tf(wg[(oc * ICN + ic + 4) * 9 + tap]);
        *(uint2*)(smem + ((((tap * 4 + k) * 4 + nt) * 32 + l) << 3)) = w2;
    }

    // ---- Prologue rows
    build_row(xn, y0 - 1, x0, smA, tid);
    build_row(xn, y0,     x0, smA, tid);

    // Bias (per-lane, 2 n-tiles x oc pair)
    const int t = lane & 3, g = lane >> 2;
    float bv[2][2];
    #pragma unroll
    for (int j = 0; j < 2; j++) {
        int oc0 = (nth * 2 + j) * 8 + 2 * t;
        bv[j][0] = bg[oc0];
        bv[j][1] = bg[oc0 + 1];
    }

    const uint2* bw = (const uint2*)smem + lane;
    const int gx = x0 + mt * 16 + g;

    #pragma unroll 1
    for (int p = 0; p < 4; p++) {
        const int y = y0 + 2 * p;           // rows y, y+1

        __syncthreads();                    // prev pair's LDS reads done
        build_row(xn, y + 1, x0, smA, tid);
        build_row(xn, y + 2, x0, smA, tid);
        __syncthreads();                    // slots y-1..y+2 ready

        float c[2][2][4];
        #pragma unroll
        for (int r = 0; r < 2; r++)
            #pragma unroll
            for (int j = 0; j < 2; j++)
                #pragma unroll
                for (int i = 0; i < 4; i++) c[r][j][i] = 0.f;

        // per-lane slot bases: + ic-lane row + m-tile px + group
        const uint32_t* sl[4];
        #pragma unroll
        for (int i = 0; i < 4; i++)
            sl[i] = smA + ((y - 1 + i + 4) & 3) * SLOT_F
                        + (lane & 3) * STRIDE + mt * 16 + (lane >> 2);

        #pragma unroll
        for (int k = 0; k < 4; k++) {
            #pragma unroll
            for (int dx = 0; dx < 3; dx++) {
                // cache 6 B frags (3 dy x 2 nt) in regs
                uint2 b[3][2];
                #pragma unroll
                for (int dy = 0; dy < 3; dy++)
                    #pragma unroll
                    for (int j = 0; j < 2; j++)
                        b[dy][j] = bw[(size_t)((((dy * 3 + dx) * 4 + k) * 4
                                                + nth * 2 + j)) * 32];

                const int ao = k * 8 * STRIDE + dx;
                uint32_t a0, a1, a2, a3;

                // slot i=0 : (dy=0, r=0)
                a0 = sl[0][ao];       a1 = sl[0][ao + 8];
                a2 = sl[0][ao + 288]; a3 = sl[0][ao + 296];
                mma8(c[0][0], a0, a1, a2, a3, b[0][0]);
                mma8(c[0][1], a0, a1, a2, a3, b[0][1]);

                // slot i=1 : (dy=1,r=0) and (dy=0,r=1)
                a0 = sl[1][ao];       a1 = sl[1][ao + 8];
                a2 = sl[1][ao + 288]; a3 = sl[1][ao + 296];
                mma8(c[0][0], a0, a1, a2, a3, b[1][0]);
                mma8(c[0][1], a0, a1, a2, a3, b[1][1]);
                mma8(c[1][0], a0, a1, a2, a3, b[0][0]);
                mma8(c[1][1], a0, a1, a2, a3, b[0][1]);

                // slot i=2 : (dy=2,r=0) and (dy=1,r=1)
                a0 = sl[2][ao];       a1 = sl[2][ao + 8];
                a2 = sl[2][ao + 288]; a3 = sl[2][ao + 296];
                mma8(c[0][0], a0, a1, a2, a3, b[2][0]);
                mma8(c[0][1], a0, a1, a2, a3, b[2][1]);
                mma8(c[1][0], a0, a1, a2, a3, b[1][0]);
                mma8(c[1][1], a0, a1, a2, a3, b[1][1]);

                // slot i=3 : (dy=2, r=1)
                a0 = sl[3][ao];       a1 = sl[3][ao + 8];
                a2 = sl[3][ao + 288]; a3 = sl[3][ao + 296];
                mma8(c[1][0], a0, a1, a2, a3, b[2][0]);
                mma8(c[1][1], a0, a1, a2, a3, b[2][1]);
            }
        }

        // ---- Epilogue: direct stores (4 oc-planes x 8 consecutive px per instr)
        #pragma unroll
        for (int j = 0; j < 2; j++) {
            int oc0 = (nth * 2 + j) * 8 + 2 * t;
            #pragma unroll
            for (int r = 0; r < 2; r++) {
                float* o = out + (((size_t)(n * OCN + oc0)) << 16)
                               + ((size_t)(y + r) << 8) + gx;
                o[0]            = c[r][j][0] + bv[j][0];
                o[(size_t)1 << 16]      = c[r][j][1] + bv[j][1];
                o[8]            = c[r][j][2] + bv[j][0];
                o[((size_t)1 << 16) + 8] = c[r][j][3] + bv[j][1];
            }
        }
    }
}

extern "C" void kernel_launch(void* const* d_in, const int* in_sizes, int n_in,
                              void* d_out, int out_size) {
    const float* x = (const float*)d_in[0];
    const float* w = (const float*)d_in[1];
    const float* b = (const float*)d_in[2];
    float* out = (float*)d_out;

    cudaFuncSetAttribute(conv3x3_tf32_mma2_kernel,
                         cudaFuncAttributeMaxDynamicSharedMemorySize, SMEM_TOTAL);

    dim3 grid(HW / SW, HW / 8, 16);   // (4, 32, 16) = 2048 CTAs
    conv3x3_tf32_mma2_kernel<<<grid, 256, SMEM_TOTAL>>>(x, w, b, out);
}

// round 5
// speedup vs baseline: 3.2766x; 1.0799x over previous
#include <cuda_runtime.h>
#include <cstdint>

// 3x3 s1 p1 conv, NCHW fp32 via mma.sync.m16n8k8 TF32.
// CTA = 64-px x-strip x 8 output rows x 1 image; 256 thr / 8 warps.
// Warp = 1 m-tile (16 px) x 2 n-tiles (16 oc) x FOUR output rows (C = 32 regs):
// each A fragment feeds up to 3 dy-taps -> 1.5 LDS-wavefronts per HMMA (was 2.33).
// A: canonical [ic][px] tiles (stride 72 -> conflict-free), 6-slot row ring.
// B: fragment-order smem, 6 frags cached in regs per (k,dx).
// Smem 92.2 KB -> 2 CTAs/SM. Epilogue: direct sector-perfect STG.32 + bias.

#define HW     256
#define ICN    32
#define OCN    32
#define SW     64            // strip width
#define XW     66            // strip + halo
#define STRIDE 72            // floats per ic row (==8 mod 32 -> conflict-free)
#define SLOT_F (ICN * STRIDE)            // 2304 floats = 9216 B
#define B_BYTES (9 * 4 * 4 * 32 * 8)     // 36864
#define SM_A    B_BYTES
#define NSLOT   6
#define SMEM_TOTAL (B_BYTES + NSLOT * SLOT_F * 4)   // 92160 B

__device__ __forceinline__ uint32_t f2tf(float f) {
    uint32_t r;
    asm("cvt.rna.tf32.f32 %0, %1;" : "=r"(r) : "f"(f));
    return r;
}

__device__ __forceinline__ void mma8(float c[4], uint32_t a0, uint32_t a1,
                                     uint32_t a2, uint32_t a3, uint2 b) {
    asm volatile(
        "mma.sync.aligned.m16n8k8.row.col.f32.tf32.tf32.f32 "
        "{%0,%1,%2,%3},{%4,%5,%6,%7},{%8,%9},{%0,%1,%2,%3};"
        : "+f"(c[0]), "+f"(c[1]), "+f"(c[2]), "+f"(c[3])
        : "r"(a0), "r"(a1), "r"(a2), "r"(a3), "r"(b.x), "r"(b.y));
}

// Stage input row yin into ring slot (yin mod 6): raw tf32 [ic][px], coalesced.
__device__ __forceinline__ void build_row(const float* __restrict__ xn, int yin,
                                          int x0, uint32_t* __restrict__ smA,
                                          int tid) {
    uint32_t* slot = smA + ((yin + NSLOT) % NSLOT) * SLOT_F;
    bool yok = ((unsigned)yin < HW);
    const float* xr = xn + ((size_t)yin << 8);
    #pragma unroll
    for (int e = tid; e < ICN * XW; e += 256) {
        int ic = e / XW;
        int px = e - ic * XW;
        int gx = x0 - 1 + px;
        float v = 0.f;
        if (yok && (unsigned)gx < HW) v = xr[((size_t)ic << 16) + gx];
        slot[ic * STRIDE + px] = f2tf(v);
    }
}

__global__ __launch_bounds__(256, 2)
void conv3x3_tf32_mma4_kernel(const float* __restrict__ xg,
                              const float* __restrict__ wg,
                              const float* __restrict__ bg,
                              float* __restrict__ out)
{
    extern __shared__ char smem[];
    uint32_t* smA = (uint32_t*)(smem + SM_A);
    const int tid  = threadIdx.x;
    const int warp = tid >> 5;
    const int lane = tid & 31;
    const int mt   = warp >> 1;     // m-tile 0..3
    const int nth  = warp & 1;      // n-tile half: nt in {2*nth, 2*nth+1}

    const int x0 = blockIdx.x * SW;
    const int y0 = blockIdx.y * 8;
    const int n  = blockIdx.z;
    const float* xn = xg + (((size_t)n * ICN) << 16);

    // ---- Stage B (fragment order), once per CTA: 4608 uint2 frags
    #pragma unroll
    for (int it = 0; it < 18; it++) {
        int idx  = tid + it * 256;
        int l    = idx & 31;
        int nt   = (idx >> 5) & 3;
        int k    = (idx >> 7) & 3;
        int tap  = idx >> 9;                    // dy*3+dx
        int oc   = nt * 8 + (l >> 2);
        int ic   = k * 8 + (l & 3);
        uint2 w2;
        w2.x = f2tf(wg[(oc * ICN + ic) * 9 + tap]);
        w2.y = f2tf(wg[(oc * ICN + ic + 4) * 9 + tap]);
        *(uint2*)(smem + ((((tap * 4 + k) * 4 + nt) * 32 + l) << 3)) = w2;
    }

    // ---- Prologue rows
    build_row(xn, y0 - 1, x0, smA, tid);
    build_row(xn, y0,     x0, smA, tid);

    // Bias (per-lane, 2 n-tiles x oc pair)
    const int t = lane & 3, g = lane >> 2;
    float bv[2][2];
    #pragma unroll
    for (int j = 0; j < 2; j++) {
        int oc0 = (nth * 2 + j) * 8 + 2 * t;
        bv[j][0] = bg[oc0];
        bv[j][1] = bg[oc0 + 1];
    }

    const uint2* bw = (const uint2*)smem + lane;
    const int gx = x0 + mt * 16 + g;
    const uint32_t lbase = (lane & 3) * STRIDE + mt * 16 + (lane >> 2);

    #pragma unroll 1
    for (int p = 0; p < 2; p++) {
        const int y = y0 + 4 * p;           // rows y .. y+3

        __syncthreads();                    // prev phase's LDS reads done
        build_row(xn, y + 1, x0, smA, tid);
        build_row(xn, y + 2, x0, smA, tid);
        build_row(xn, y + 3, x0, smA, tid);
        build_row(xn, y + 4, x0, smA, tid);
        __syncthreads();                    // slots y-1 .. y+4 ready

        float c[4][2][4];
        #pragma unroll
        for (int r = 0; r < 4; r++)
            #pragma unroll
            for (int j = 0; j < 2; j++)
                #pragma unroll
                for (int i = 0; i < 4; i++) c[r][j][i] = 0.f;

        // slot offsets for input rows y-1+i, i=0..5
        uint32_t so[NSLOT];
        #pragma unroll
        for (int i = 0; i < NSLOT; i++)
            so[i] = ((y - 1 + i + NSLOT) % NSLOT) * SLOT_F + lbase;

        #pragma unroll
        for (int k = 0; k < 4; k++) {
            #pragma unroll
            for (int dx = 0; dx < 3; dx++) {
                // cache 6 B frags (3 dy x 2 nt) in regs
                uint2 b[3][2];
                #pragma unroll
                for (int dy = 0; dy < 3; dy++)
                    #pragma unroll
                    for (int j = 0; j < 2; j++)
                        b[dy][j] = bw[(size_t)((((dy * 3 + dx) * 4 + k) * 4
                                                + nth * 2 + j)) * 32];

                const int ao = k * 8 * STRIDE + dx;

                #pragma unroll
                for (int i = 0; i < NSLOT; i++) {
                    const uint32_t* s = smA + so[i] + ao;
                    uint32_t a0 = s[0], a1 = s[8], a2 = s[288], a3 = s[296];
                    #pragma unroll
                    for (int dy = 0; dy < 3; dy++) {
                        int rl = i - dy;             // rl + dy == i
                        if (rl >= 0 && rl < 4) {
                            mma8(c[rl][0], a0, a1, a2, a3, b[dy][0]);
                            mma8(c[rl][1], a0, a1, a2, a3, b[dy][1]);
                        }
                    }
                }
            }
        }

        // ---- Epilogue: direct stores (4 oc-planes x 8 consecutive px per instr)
        #pragma unroll
        for (int rl = 0; rl < 4; rl++) {
            #pragma unroll
            for (int j = 0; j < 2; j++) {
                int oc0 = (nth * 2 + j) * 8 + 2 * t;
                float* o = out + (((size_t)(n * OCN + oc0)) << 16)
                               + ((size_t)(y + rl) << 8) + gx;
                o[0]                     = c[rl][j][0] + bv[j][0];
                o[(size_t)1 << 16]       = c[rl][j][1] + bv[j][1];
                o[8]                     = c[rl][j][2] + bv[j][0];
                o[((size_t)1 << 16) + 8] = c[rl][j][3] + bv[j][1];
            }
        }
    }
}

extern "C" void kernel_launch(void* const* d_in, const int* in_sizes, int n_in,
                              void* d_out, int out_size) {
    const float* x = (const float*)d_in[0];
    const float* w = (const float*)d_in[1];
    const float* b = (const float*)d_in[2];
    float* out = (float*)d_out;

    cudaFuncSetAttribute(conv3x3_tf32_mma4_kernel,
                         cudaFuncAttributeMaxDynamicSharedMemorySize, SMEM_TOTAL);

    dim3 grid(HW / SW, HW / 8, 16);   // (4, 32, 16) = 2048 CTAs
    conv3x3_tf32_mma4_kernel<<<grid, 256, SMEM_TOTAL>>>(x, w, b, out);
}

// round 6
// speedup vs baseline: 4.7387x; 1.4462x over previous
#include <cuda_runtime.h>
#include <cuda_fp16.h>
#include <cstdint>

// 3x3 s1 p1 conv, NCHW fp32 via mma.sync.m16n8k16 FP16 (f32 accumulate).
// fp16 mantissa == tf32 mantissa (10 bits); inputs unit-normal -> same rel_err
// as tf32 (~3e-4) but 2x K per HMMA: tensor work, A/B LDS, and STS all halve.
// CTA = 64-px x-strip x 16 output rows x 1 image; 256 thr / 8 warps.
// Warp = 1 m-tile (16 px) x 2 n-tiles (16 oc) x 4 output rows per phase.
// A: half2-packed [ic/2][px] tiles (stride 72 -> conflict-free), 6-slot ring.
// B: fragment-order smem. Smem 46 KB -> 2 CTAs/SM. Direct STG.32 epilogue.

#define HW     256
#define ICN    32
#define OCN    32
#define SW     64            // strip width
#define XW     66            // strip + halo
#define YCH    16            // output rows per CTA
#define STRIDE 72            // u32 per kp row (==8 mod 32 -> conflict-free)
#define KPN    16            // ic/2 packed rows
#define SLOT_U (KPN * STRIDE)              // 1152 u32 = 4608 B
#define B_BYTES (9 * 2 * 4 * 32 * 8)       // tap*kstep*ntile*lane*uint2 = 18432
#define SM_A    B_BYTES
#define NSLOT   6
#define SMEM_TOTAL (B_BYTES + NSLOT * SLOT_U * 4)   // 46080 B

__device__ __forceinline__ uint32_t pack_h2(float a, float b) {
    uint32_t r;
    asm("cvt.rn.f16x2.f32 %0, %2, %1;" : "=r"(r) : "f"(a), "f"(b));
    return r;   // lo half = a, hi half = b
}

__device__ __forceinline__ void mma16(float c[4], uint32_t a0, uint32_t a1,
                                      uint32_t a2, uint32_t a3, uint2 b) {
    asm volatile(
        "mma.sync.aligned.m16n8k16.row.col.f32.f16.f16.f32 "
        "{%0,%1,%2,%3},{%4,%5,%6,%7},{%8,%9},{%0,%1,%2,%3};"
        : "+f"(c[0]), "+f"(c[1]), "+f"(c[2]), "+f"(c[3])
        : "r"(a0), "r"(a1), "r"(a2), "r"(a3), "r"(b.x), "r"(b.y));
}

// Stage input row yin into ring slot (yin mod 6): half2-packed [ic/2][px].
__device__ __forceinline__ void build_row(const float* __restrict__ xn, int yin,
                                          int x0, uint32_t* __restrict__ smA,
                                          int tid) {
    uint32_t* slot = smA + ((yin + 2 * NSLOT) % NSLOT) * SLOT_U;
    bool yok = ((unsigned)yin < HW);
    const float* xr = xn + ((size_t)yin << 8);
    #pragma unroll
    for (int e = tid; e < KPN * XW; e += 256) {
        int kp = e / XW;
        int px = e - kp * XW;
        int gx = x0 - 1 + px;
        float v0 = 0.f, v1 = 0.f;
        if (yok && (unsigned)gx < HW) {
            const float* p = xr + (((size_t)kp * 2) << 16) + gx;
            v0 = p[0];
            v1 = p[1 << 16];
        }
        slot[kp * STRIDE + px] = pack_h2(v0, v1);
    }
}

__global__ __launch_bounds__(256, 2)
void conv3x3_f16_mma_kernel(const float* __restrict__ xg,
                            const float* __restrict__ wg,
                            const float* __restrict__ bg,
                            float* __restrict__ out)
{
    extern __shared__ char smem[];
    uint32_t* smA = (uint32_t*)(smem + SM_A);
    const int tid  = threadIdx.x;
    const int warp = tid >> 5;
    const int lane = tid & 31;
    const int mt   = warp >> 1;     // m-tile 0..3
    const int nth  = warp & 1;      // n-tile half

    const int x0 = blockIdx.x * SW;
    const int y0 = blockIdx.y * YCH;
    const int n  = blockIdx.z;
    const float* xn = xg + (((size_t)n * ICN) << 16);

    // ---- Stage B (fragment order): 2304 uint2 frags, once per CTA
    #pragma unroll
    for (int it = 0; it < 9; it++) {
        int idx  = tid + it * 256;
        int l    = idx & 31;
        int nt   = (idx >> 5) & 3;
        int k0   = (idx >> 7) & 1;
        int tap  = idx >> 8;                    // dy*3+dx
        int oc   = nt * 8 + (l >> 2);
        int ic0  = k0 * 16 + (l & 3) * 2;
        const float* wp = wg + (size_t)oc * ICN * 9 + tap;
        uint2 w2;
        w2.x = pack_h2(wp[(size_t)ic0 * 9],       wp[(size_t)(ic0 + 1) * 9]);
        w2.y = pack_h2(wp[(size_t)(ic0 + 8) * 9], wp[(size_t)(ic0 + 9) * 9]);
        *(uint2*)(smem + ((((tap * 2 + k0) * 4 + nt) * 32 + l) << 3)) = w2;
    }

    // ---- Prologue rows
    build_row(xn, y0 - 1, x0, smA, tid);
    build_row(xn, y0,     x0, smA, tid);

    // Bias (per-lane, 2 n-tiles x oc pair)
    const int t = lane & 3, g = lane >> 2;
    float bv[2][2];
    #pragma unroll
    for (int j = 0; j < 2; j++) {
        int oc0 = (nth * 2 + j) * 8 + 2 * t;
        bv[j][0] = bg[oc0];
        bv[j][1] = bg[oc0 + 1];
    }

    const uint2* bw = (const uint2*)smem + lane;
    const int gx = x0 + mt * 16 + g;
    const uint32_t lbase = t * STRIDE + mt * 16 + g;

    #pragma unroll 1
    for (int p = 0; p < YCH / 4; p++) {
        const int y = y0 + 4 * p;           // rows y .. y+3

        __syncthreads();                    // prev phase's LDS reads done
        build_row(xn, y + 1, x0, smA, tid);
        build_row(xn, y + 2, x0, smA, tid);
        build_row(xn, y + 3, x0, smA, tid);
        build_row(xn, y + 4, x0, smA, tid);
        __syncthreads();                    // slots y-1 .. y+4 ready

        float c[4][2][4];
        #pragma unroll
        for (int r = 0; r < 4; r++)
            #pragma unroll
            for (int j = 0; j < 2; j++)
                #pragma unroll
                for (int i = 0; i < 4; i++) c[r][j][i] = 0.f;

        uint32_t so[NSLOT];
        #pragma unroll
        for (int i = 0; i < NSLOT; i++)
            so[i] = ((y - 1 + i + 2 * NSLOT) % NSLOT) * SLOT_U + lbase;

        #pragma unroll
        for (int k0 = 0; k0 < 2; k0++) {
            #pragma unroll
            for (int dx = 0; dx < 3; dx++) {
                // cache 6 B frags (3 dy x 2 nt) in regs
                uint2 b[3][2];
                #pragma unroll
                for (int dy = 0; dy < 3; dy++)
                    #pragma unroll
                    for (int j = 0; j < 2; j++)
                        b[dy][j] = bw[(size_t)((((dy * 3 + dx) * 2 + k0) * 4
                                                + nth * 2 + j)) * 32];

                const int ao = k0 * 8 * STRIDE + dx;

                #pragma unroll
                for (int i = 0; i < NSLOT; i++) {
                    const uint32_t* s = smA + so[i] + ao;
                    uint32_t a0 = s[0], a1 = s[8];
                    uint32_t a2 = s[4 * STRIDE], a3 = s[4 * STRIDE + 8];
                    #pragma unroll
                    for (int dy = 0; dy < 3; dy++) {
                        int rl = i - dy;
                        if (rl >= 0 && rl < 4) {
                            mma16(c[rl][0], a0, a1, a2, a3, b[dy][0]);
                            mma16(c[rl][1], a0, a1, a2, a3, b[dy][1]);
                        }
                    }
                }
            }
        }

        // ---- Epilogue: direct stores (sector-perfect STG.32)
        #pragma unroll
        for (int rl = 0; rl < 4; rl++) {
            #pragma unroll
            for (int j = 0; j < 2; j++) {
                int oc0 = (nth * 2 + j) * 8 + 2 * t;
                float* o = out + (((size_t)(n * OCN + oc0)) << 16)
                               + ((size_t)(y + rl) << 8) + gx;
                o[0]                     = c[rl][j][0] + bv[j][0];
                o[(size_t)1 << 16]       = c[rl][j][1] + bv[j][1];
                o[8]                     = c[rl][j][2] + bv[j][0];
                o[((size_t)1 << 16) + 8] = c[rl][j][3] + bv[j][1];
            }
        }
    }
}

extern "C" void kernel_launch(void* const* d_in, const int* in_sizes, int n_in,
                              void* d_out, int out_size) {
    const float* x = (const float*)d_in[0];
    const float* w = (const float*)d_in[1];
    const float* b = (const float*)d_in[2];
    float* out = (float*)d_out;

    cudaFuncSetAttribute(conv3x3_f16_mma_kernel,
                         cudaFuncAttributeMaxDynamicSharedMemorySize, SMEM_TOTAL);

    dim3 grid(HW / SW, HW / YCH, 16);   // (4, 16, 16) = 1024 CTAs
    conv3x3_f16_mma_kernel<<<grid, 256, SMEM_TOTAL>>>(x, w, b, out);
}